// round 6
// baseline (speedup 1.0000x reference)
#include <cuda_runtime.h>
#include <cstdint>

// GraphNN: N_NODES=12, WIDTH=128, BATCH=16384, N_EDGES=66.
// o_1 = x;  o_v = sum_{u<v} relu(o_u @ W[e(u,v)] + b[e(u,v)]),  answer = o_12.
// Strategy: 11 sequential step kernels (one per node v), tf32 mma.sync tensor
// cores, per-edge fp32 accumulation with fused relu+bias+sum.
// Intermediates o_2..o_11 live in a __device__ scratch (allowed; no allocs).

#define BATCH   16384
#define WIDTH   128
#define MT      64          // M tile per CTA
#define KC      64          // K chunk
#define THREADS 256
#define AS_STRIDE (KC + 4)      // 68 floats  -> A-frag LDS conflict-free
#define WS_STRIDE (WIDTH + 8)   // 136 floats -> B-frag LDS conflict-free
#define SMEM_BYTES ((MT * AS_STRIDE + KC * WS_STRIDE) * 4)   // 52224 B

__device__ float g_scratch[10 * (size_t)BATCH * WIDTH];   // nodes 2..11

__device__ __forceinline__ float to_tf32(float x) {
    float r;
    asm("cvt.rna.tf32.f32 %0, %1;" : "=f"(r) : "f"(x));
    return r;
}

__device__ __forceinline__ void mma_tf32(float c[4], const uint32_t a[4],
                                         const uint32_t b[2]) {
    asm volatile(
        "mma.sync.aligned.m16n8k8.row.col.f32.tf32.tf32.f32 "
        "{%0,%1,%2,%3}, {%4,%5,%6,%7}, {%8,%9}, {%0,%1,%2,%3};"
        : "+f"(c[0]), "+f"(c[1]), "+f"(c[2]), "+f"(c[3])
        : "r"(a[0]), "r"(a[1]), "r"(a[2]), "r"(a[3]), "r"(b[0]), "r"(b[1]));
}

__global__ void __launch_bounds__(THREADS, 2)
graphnn_step(const float* __restrict__ x, const float* __restrict__ W,
             const float* __restrict__ bias, float* __restrict__ dout, int v)
{
    extern __shared__ float smem[];
    float (*As)[AS_STRIDE] = (float (*)[AS_STRIDE])smem;                  // [MT][68]
    float (*Ws)[WS_STRIDE] = (float (*)[WS_STRIDE])(smem + MT * AS_STRIDE); // [KC][136]

    const int m0   = blockIdx.x * MT;
    const int tid  = threadIdx.x;
    const int lane = tid & 31;
    const int warp = tid >> 5;
    const int g    = lane >> 2;   // 0..7
    const int t    = lane & 3;    // 0..3
    const int wm   = warp >> 2;   // 0..1  (warp tile rows: wm*32)
    const int wn   = warp & 3;    // 0..3  (warp tile cols: wn*32)

    const int p     = v - 1;
    const int start = (v - 2) * (v - 1) / 2;

    // running per-node sum
    float fin[2][4][4];
    #pragma unroll
    for (int mf = 0; mf < 2; ++mf)
        #pragma unroll
        for (int nf = 0; nf < 4; ++nf)
            #pragma unroll
            for (int j = 0; j < 4; ++j) fin[mf][nf][j] = 0.f;

    for (int u = 0; u < p; ++u) {
        const float* A  = (u == 0) ? x
                                   : (g_scratch + (size_t)(u - 1) * BATCH * WIDTH);
        const float* Wu = W + (size_t)(start + u) * WIDTH * WIDTH;

        float acc[2][4][4];   // per-edge accumulator (pre-relu)
        #pragma unroll
        for (int mf = 0; mf < 2; ++mf)
            #pragma unroll
            for (int nf = 0; nf < 4; ++nf)
                #pragma unroll
                for (int j = 0; j < 4; ++j) acc[mf][nf][j] = 0.f;

        #pragma unroll
        for (int kc = 0; kc < WIDTH; kc += KC) {
            __syncthreads();   // protect smem reads of previous chunk/edge
            // ---- load A tile: MT x KC, coalesced float4, convert to tf32 ----
            #pragma unroll
            for (int i = 0; i < (MT * KC) / (THREADS * 4); ++i) {    // 4
                int f = tid + i * THREADS;          // float4 index 0..1023
                int r = f >> 4;
                int c = (f & 15) << 2;
                float4 va = *(const float4*)(A + (size_t)(m0 + r) * WIDTH + kc + c);
                float4 vt = make_float4(to_tf32(va.x), to_tf32(va.y),
                                        to_tf32(va.z), to_tf32(va.w));
                *(float4*)&As[r][c] = vt;
            }
            // ---- load W tile: KC x WIDTH ----
            #pragma unroll
            for (int i = 0; i < (KC * WIDTH) / (THREADS * 4); ++i) { // 8
                int f = tid + i * THREADS;          // 0..2047
                int r = f >> 5;
                int c = (f & 31) << 2;
                float4 vw = *(const float4*)(Wu + (size_t)(kc + r) * WIDTH + c);
                float4 vt = make_float4(to_tf32(vw.x), to_tf32(vw.y),
                                        to_tf32(vw.z), to_tf32(vw.w));
                *(float4*)&Ws[r][c] = vt;
            }
            __syncthreads();

            // ---- 8 k-steps of m16n8k8 tf32 ----
            #pragma unroll
            for (int kk = 0; kk < KC / 8; ++kk) {
                const int k = kk * 8;
                uint32_t afr[2][4];
                #pragma unroll
                for (int mf = 0; mf < 2; ++mf) {
                    const int rb = wm * 32 + mf * 16;
                    afr[mf][0] = __float_as_uint(As[rb + g    ][k + t    ]);
                    afr[mf][1] = __float_as_uint(As[rb + g + 8][k + t    ]);
                    afr[mf][2] = __float_as_uint(As[rb + g    ][k + t + 4]);
                    afr[mf][3] = __float_as_uint(As[rb + g + 8][k + t + 4]);
                }
                uint32_t bfr[4][2];
                #pragma unroll
                for (int nf = 0; nf < 4; ++nf) {
                    const int cn = wn * 32 + nf * 8 + g;
                    bfr[nf][0] = __float_as_uint(Ws[k + t    ][cn]);
                    bfr[nf][1] = __float_as_uint(Ws[k + t + 4][cn]);
                }
                #pragma unroll
                for (int mf = 0; mf < 2; ++mf)
                    #pragma unroll
                    for (int nf = 0; nf < 4; ++nf)
                        mma_tf32(acc[mf][nf], afr[mf], bfr[nf]);
            }
        }

        // ---- per-edge epilogue: fin += relu(acc + bias) ----
        #pragma unroll
        for (int nf = 0; nf < 4; ++nf) {
            const int n  = wn * 32 + nf * 8 + t * 2;
            const float b0 = bias[(size_t)(start + u) * WIDTH + n];
            const float b1 = bias[(size_t)(start + u) * WIDTH + n + 1];
            #pragma unroll
            for (int mf = 0; mf < 2; ++mf) {
                fin[mf][nf][0] += fmaxf(acc[mf][nf][0] + b0, 0.f);
                fin[mf][nf][1] += fmaxf(acc[mf][nf][1] + b1, 0.f);
                fin[mf][nf][2] += fmaxf(acc[mf][nf][2] + b0, 0.f);
                fin[mf][nf][3] += fmaxf(acc[mf][nf][3] + b1, 0.f);
            }
        }
    }

    // ---- store node output (coalesced float2) ----
    float* O = (v == 12) ? dout : (g_scratch + (size_t)(v - 2) * BATCH * WIDTH);
    #pragma unroll
    for (int mf = 0; mf < 2; ++mf) {
        #pragma unroll
        for (int nf = 0; nf < 4; ++nf) {
            const int row = m0 + wm * 32 + mf * 16 + g;
            const int col = wn * 32 + nf * 8 + t * 2;
            *(float2*)&O[(size_t)row * WIDTH + col] =
                make_float2(fin[mf][nf][0], fin[mf][nf][1]);
            *(float2*)&O[(size_t)(row + 8) * WIDTH + col] =
                make_float2(fin[mf][nf][2], fin[mf][nf][3]);
        }
    }
}

extern "C" void kernel_launch(void* const* d_in, const int* in_sizes, int n_in,
                              void* d_out, int out_size) {
    const float* x = (const float*)d_in[0];   // (16384, 128)
    const float* W = (const float*)d_in[1];   // (66, 128, 128)
    const float* b = (const float*)d_in[2];   // (66, 128)
    float* out = (float*)d_out;               // (16384, 128)

    static bool attr_set = false;
    if (!attr_set) {
        cudaFuncSetAttribute(graphnn_step,
                             cudaFuncAttributeMaxDynamicSharedMemorySize,
                             SMEM_BYTES);
        attr_set = true;
    }

    for (int v = 2; v <= 12; ++v) {
        graphnn_step<<<BATCH / MT, THREADS, SMEM_BYTES>>>(x, W, b, out, v);
    }
}

// round 7
// speedup vs baseline: 1.1488x; 1.1488x over previous
#include <cuda_runtime.h>
#include <cstdint>

// GraphNN: N_NODES=12, WIDTH=128, BATCH=16384, N_EDGES=66.
// o_v = sum_{u<v} relu(o_u @ W[e(u,v)] + b[e(u,v)]);  answer = o_12.
// R6: tf32 conversion hoisted to a one-time pre-pass (x, W) + tf32-rounded
// scratch stores; 2-stage cp.async pipeline over flat (edge,chunk) space.

#define BATCH   16384
#define WIDTH   128
#define MT      64
#define KC      64
#define THREADS 256
#define AS_STRIDE (KC + 4)        // 68
#define WS_STRIDE (WIDTH + 8)     // 136
#define STAGE_FLOATS (MT * AS_STRIDE + KC * WS_STRIDE)   // 13056
#define SMEM_BYTES (2 * STAGE_FLOATS * 4)                // 104448 B

__device__ float g_scratch[10 * (size_t)BATCH * WIDTH];  // nodes 2..11 (tf32-rounded)
__device__ float g_xc[(size_t)BATCH * WIDTH];            // x, tf32-rounded
__device__ float g_Wc[66 * (size_t)WIDTH * WIDTH];       // W, tf32-rounded

__device__ __forceinline__ float to_tf32(float x) {
    float r;
    asm("cvt.rna.tf32.f32 %0, %1;" : "=f"(r) : "f"(x));
    return r;
}

__device__ __forceinline__ void cp_async16(float* smem_ptr, const float* gmem_ptr) {
    uint32_t s = (uint32_t)__cvta_generic_to_shared(smem_ptr);
    asm volatile("cp.async.cg.shared.global [%0], [%1], 16;" :: "r"(s), "l"(gmem_ptr));
}

__device__ __forceinline__ void mma_tf32(float c[4], const uint32_t a[4],
                                         const uint32_t b[2]) {
    asm volatile(
        "mma.sync.aligned.m16n8k8.row.col.f32.tf32.tf32.f32 "
        "{%0,%1,%2,%3}, {%4,%5,%6,%7}, {%8,%9}, {%0,%1,%2,%3};"
        : "+f"(c[0]), "+f"(c[1]), "+f"(c[2]), "+f"(c[3])
        : "r"(a[0]), "r"(a[1]), "r"(a[2]), "r"(a[3]), "r"(b[0]), "r"(b[1]));
}

// One-time pre-pass: tf32-round x and W into device scratch.
__global__ void convert_pre(const float* __restrict__ x, const float* __restrict__ W) {
    const size_t nx = (size_t)BATCH * WIDTH / 4;          // float4 count
    const size_t nw = 66 * (size_t)WIDTH * WIDTH / 4;
    const size_t total = nx + nw;
    for (size_t i = (size_t)blockIdx.x * blockDim.x + threadIdx.x; i < total;
         i += (size_t)gridDim.x * blockDim.x) {
        if (i < nx) {
            float4 v = ((const float4*)x)[i];
            ((float4*)g_xc)[i] = make_float4(to_tf32(v.x), to_tf32(v.y),
                                             to_tf32(v.z), to_tf32(v.w));
        } else {
            float4 v = ((const float4*)W)[i - nx];
            ((float4*)g_Wc)[i - nx] = make_float4(to_tf32(v.x), to_tf32(v.y),
                                                  to_tf32(v.z), to_tf32(v.w));
        }
    }
}

__global__ void __launch_bounds__(THREADS, 2)
graphnn_step(const float* __restrict__ bias, float* __restrict__ dout, int v)
{
    extern __shared__ float smem[];
    // stage s: A at smem + s*STAGE_FLOATS, W at +MT*AS_STRIDE
    const int m0   = blockIdx.x * MT;
    const int tid  = threadIdx.x;
    const int lane = tid & 31;
    const int warp = tid >> 5;
    const int g    = lane >> 2;
    const int t    = lane & 3;
    const int wm   = warp >> 2;
    const int wn   = warp & 3;

    const int p      = v - 1;
    const int start  = (v - 2) * (v - 1) / 2;
    const int nchunk = 2 * p;

    // per-thread precomputed load indices
    const int ar[4] = { (tid + 0*THREADS) >> 4, (tid + 1*THREADS) >> 4,
                        (tid + 2*THREADS) >> 4, (tid + 3*THREADS) >> 4 };
    const int ac[4] = { ((tid + 0*THREADS) & 15) << 2, ((tid + 1*THREADS) & 15) << 2,
                        ((tid + 2*THREADS) & 15) << 2, ((tid + 3*THREADS) & 15) << 2 };

    float fin[2][4][4];
    #pragma unroll
    for (int mf = 0; mf < 2; ++mf)
        #pragma unroll
        for (int nf = 0; nf < 4; ++nf)
            #pragma unroll
            for (int j = 0; j < 4; ++j) fin[mf][nf][j] = 0.f;

    float acc[2][4][4];

    // ---- issue cp.async for chunk idx into buffer idx&1 ----
    auto issue = [&](int idx) {
        const int u   = idx >> 1;
        const int kc  = (idx & 1) << 6;
        float* As = smem + (idx & 1) * STAGE_FLOATS;
        float* Ws = As + MT * AS_STRIDE;
        const float* A  = (u == 0) ? g_xc
                                   : (g_scratch + (size_t)(u - 1) * BATCH * WIDTH);
        const float* Wu = g_Wc + (size_t)(start + u) * WIDTH * WIDTH;
        #pragma unroll
        for (int i = 0; i < 4; ++i)     // A: 64x64
            cp_async16(As + ar[i] * AS_STRIDE + ac[i],
                       A + (size_t)(m0 + ar[i]) * WIDTH + kc + ac[i]);
        #pragma unroll
        for (int i = 0; i < 8; ++i) {   // W: 64x128
            int f = tid + i * THREADS;
            int r = f >> 5;
            int c = (f & 31) << 2;
            cp_async16(Ws + r * WS_STRIDE + c,
                       Wu + (size_t)(kc + r) * WIDTH + c);
        }
        asm volatile("cp.async.commit_group;");
    };

    issue(0);

    for (int idx = 0; idx < nchunk; ++idx) {
        const int buf = idx & 1;
        if ((idx & 1) == 0) {           // new edge: reset per-edge accumulator
            #pragma unroll
            for (int mf = 0; mf < 2; ++mf)
                #pragma unroll
                for (int nf = 0; nf < 4; ++nf)
                    #pragma unroll
                    for (int j = 0; j < 4; ++j) acc[mf][nf][j] = 0.f;
        }
        if (idx + 1 < nchunk) {
            issue(idx + 1);
            asm volatile("cp.async.wait_group 1;");
        } else {
            asm volatile("cp.async.wait_group 0;");
        }
        __syncthreads();

        const float (*As)[AS_STRIDE] =
            (const float (*)[AS_STRIDE])(smem + buf * STAGE_FLOATS);
        const float (*Ws)[WS_STRIDE] =
            (const float (*)[WS_STRIDE])(smem + buf * STAGE_FLOATS + MT * AS_STRIDE);

        #pragma unroll
        for (int kk = 0; kk < KC / 8; ++kk) {
            const int k = kk * 8;
            uint32_t afr[2][4];
            #pragma unroll
            for (int mf = 0; mf < 2; ++mf) {
                const int rb = wm * 32 + mf * 16;
                afr[mf][0] = __float_as_uint(As[rb + g    ][k + t    ]);
                afr[mf][1] = __float_as_uint(As[rb + g + 8][k + t    ]);
                afr[mf][2] = __float_as_uint(As[rb + g    ][k + t + 4]);
                afr[mf][3] = __float_as_uint(As[rb + g + 8][k + t + 4]);
            }
            uint32_t bfr[4][2];
            #pragma unroll
            for (int nf = 0; nf < 4; ++nf) {
                const int cn = wn * 32 + nf * 8 + g;
                bfr[nf][0] = __float_as_uint(Ws[k + t    ][cn]);
                bfr[nf][1] = __float_as_uint(Ws[k + t + 4][cn]);
            }
            #pragma unroll
            for (int mf = 0; mf < 2; ++mf)
                #pragma unroll
                for (int nf = 0; nf < 4; ++nf)
                    mma_tf32(acc[mf][nf], afr[mf], bfr[nf]);
        }
        __syncthreads();   // all warps done with buf before it is overwritten

        if (idx & 1) {      // edge complete: fin += relu(acc + bias)
            const int u = idx >> 1;
            #pragma unroll
            for (int nf = 0; nf < 4; ++nf) {
                const int n  = wn * 32 + nf * 8 + t * 2;
                const float b0 = bias[(size_t)(start + u) * WIDTH + n];
                const float b1 = bias[(size_t)(start + u) * WIDTH + n + 1];
                #pragma unroll
                for (int mf = 0; mf < 2; ++mf) {
                    fin[mf][nf][0] += fmaxf(acc[mf][nf][0] + b0, 0.f);
                    fin[mf][nf][1] += fmaxf(acc[mf][nf][1] + b1, 0.f);
                    fin[mf][nf][2] += fmaxf(acc[mf][nf][2] + b0, 0.f);
                    fin[mf][nf][3] += fmaxf(acc[mf][nf][3] + b1, 0.f);
                }
            }
        }
    }

    // ---- store node output; scratch stores are tf32-rounded (consumed as tf32) ----
    const bool last = (v == 12);
    float* O = last ? dout : (g_scratch + (size_t)(v - 2) * BATCH * WIDTH);
    #pragma unroll
    for (int mf = 0; mf < 2; ++mf) {
        #pragma unroll
        for (int nf = 0; nf < 4; ++nf) {
            const int row = m0 + wm * 32 + mf * 16 + g;
            const int col = wn * 32 + nf * 8 + t * 2;
            float v00 = fin[mf][nf][0], v01 = fin[mf][nf][1];
            float v10 = fin[mf][nf][2], v11 = fin[mf][nf][3];
            if (!last) {
                v00 = to_tf32(v00); v01 = to_tf32(v01);
                v10 = to_tf32(v10); v11 = to_tf32(v11);
            }
            *(float2*)&O[(size_t)row * WIDTH + col]       = make_float2(v00, v01);
            *(float2*)&O[(size_t)(row + 8) * WIDTH + col] = make_float2(v10, v11);
        }
    }
}

extern "C" void kernel_launch(void* const* d_in, const int* in_sizes, int n_in,
                              void* d_out, int out_size) {
    const float* x = (const float*)d_in[0];   // (16384, 128)
    const float* W = (const float*)d_in[1];   // (66, 128, 128)
    const float* b = (const float*)d_in[2];   // (66, 128)
    float* out = (float*)d_out;               // (16384, 128)

    static bool attr_set = false;
    if (!attr_set) {
        cudaFuncSetAttribute(graphnn_step,
                             cudaFuncAttributeMaxDynamicSharedMemorySize,
                             SMEM_BYTES);
        attr_set = true;
    }

    convert_pre<<<1024, 256>>>(x, W);
    for (int v = 2; v <= 12; ++v) {
        graphnn_step<<<BATCH / MT, THREADS, SMEM_BYTES>>>(b, out, v);
    }
}